// round 5
// baseline (speedup 1.0000x reference)
#include <cuda_runtime.h>
#include <cuda_bf16.h>
#include <cstdint>

#define R 512
#define T 65536
#define KMAX 32
#define XCHUNK 1024            // steps per x chunk (8KB)

// ---------------- device scratch ----------------
__device__ int   g_tcol[R * KMAX];
__device__ float g_tval[R * KMAX];
__device__ float g_val[KMAX * R];       // [slot][thread]
__device__ int   g_col[KMAX * R];
__device__ int   g_rowof[R];
__device__ int   g_plen[R];             // true nnz per thread (for safety guard)
__device__ int   g_wclass[R / 32];
__device__ float g_states[(size_t)T * R];

// ---------------- Kernel A: extract + length-sort + bank-sorted minimal ELL ----------------
__global__ void __launch_bounds__(R, 1) esn_extract(const float* __restrict__ W) {
    __shared__ int s_len[R];      // row-indexed nnz
    __shared__ int s_pos[R];
    __shared__ int s_rowof[R];
    __shared__ int s_cnt[KMAX + 1];
    __shared__ int s_base[KMAX + 1];

    const int p = threadIdx.x;

    int len = 0;
    for (int j = 0; j < R; ++j) {
        float v = W[p * R + j];
        if (v != 0.0f) {
            if (len < KMAX) { g_tcol[p * KMAX + len] = j; g_tval[p * KMAX + len] = v; }
            ++len;
        }
    }
    if (len > KMAX) len = KMAX;
    s_len[p] = len;
    if (p <= KMAX) s_cnt[p] = 0;
    __syncthreads();

    atomicAdd(&s_cnt[len], 1);
    __syncthreads();
    if (p == 0) {
        int acc = 0;
        for (int l = 0; l <= KMAX; ++l) { s_base[l] = acc; acc += s_cnt[l]; }
    }
    __syncthreads();
    int pos = atomicAdd(&s_base[len], 1);
    s_pos[p] = pos;
    s_rowof[pos] = p;
    __syncthreads();

    // thread p owns sorted position p
    const int row   = s_rowof[p];
    const int mylen = s_len[row];         // row-indexed (never overwritten)
    const int wid   = p >> 5;
    int cls = s_len[s_rowof[(wid << 5) | 31]];   // warp max (ascending sort)
    if (cls < 1) cls = 1;
    // round up to available dispatch class: 1..16, then multiples of 4
    int clsd = (cls <= 16) ? cls : ((cls + 3) & ~3);
    if (clsd > KMAX) clsd = KMAX;
    if ((p & 31) == 0) g_wclass[wid] = clsd;
    g_rowof[p] = row;
    g_plen[p]  = mylen;

    int   cols[KMAX];
    float vals[KMAX];
    for (int k = 0; k < mylen; ++k) {
        cols[k] = s_pos[g_tcol[row * KMAX + k]];
        vals[k] = g_tval[row * KMAX + k];
    }
    for (int k = mylen; k < clsd; ++k) { cols[k] = p; vals[k] = 0.0f; }  // own-bank pad

    // lane-relative bank sort to spread conflicts across slots
    const int lane = p & 31;
    for (int a = 1; a < clsd; ++a) {
        int c = cols[a]; float v = vals[a];
        int key = ((c & 31) - lane) & 31;
        int b = a - 1;
        while (b >= 0 && ((((cols[b] & 31) - lane) & 31) > key)) {
            cols[b + 1] = cols[b]; vals[b + 1] = vals[b]; --b;
        }
        cols[b + 1] = c; vals[b + 1] = v;
    }
    for (int k = 0; k < clsd; ++k) {
        g_val[k * R + p] = vals[k];
        g_col[k * R + p] = cols[k];
    }
}

// 5-op tanh: 1 - 2/(exp2(2*log2e*x)+1); ~1e-6 abs err
__device__ __forceinline__ float tanh_acc(float x) {
    float e = exp2f(2.885390082f * x);
    float r;
    asm("rcp.approx.f32 %0, %1;" : "=f"(r) : "f"(e + 1.0f));
    return fmaf(-2.0f, r, 1.0f);
}

// ---------------- templated recurrence body ----------------
template <int NK>
__device__ __forceinline__ float run_loop(const float4* __restrict__ xg4,
                                          float* __restrict__ hbuf,
                                          float2* __restrict__ xs2,   // [2*XCHUNK] ring
                                          int p, int mylen, float w0, float w1)
{
    float rv[NK];
    int   rc[NK];
#pragma unroll
    for (int k = 0; k < NK; ++k) {
        rv[k] = g_val[k * R + p];
        rc[k] = g_col[k * R + p] << 2;
    }

    float* myst = g_states + p;
    float2 xv = xs2[0];
    float hn = 0.0f;

    for (int t = 0; t < T; ++t) {
        const char* hr = (const char*)(hbuf + ((t & 1) << 9));
        float acc0 = w0 * xv.x;
        float acc1 = w1 * xv.y;
#pragma unroll
        for (int k = 0; k < NK; ++k) {
            float hv = *(const float*)(hr + rc[k]);
            if (k & 1) acc1 = fmaf(rv[k], hv, acc1);
            else       acc0 = fmaf(rv[k], hv, acc0);
        }
        if (NK < mylen) {   // impossible for this data (cls = warp max); backstop
            for (int k = NK; k < mylen; ++k)
                acc0 = fmaf(g_val[k * R + p], ((const float*)hr)[g_col[k * R + p]], acc0);
        }
        hn = tanh_acc(acc0 + acc1);
        hbuf[(((t + 1) & 1) << 9) + p] = hn;

        asm volatile("bar.arrive 0, 1024;" ::: "memory");
        // ---- off-critical-path window ----
        __stcs(myst, hn);  myst += R;                   // streaming states STG
        if ((t & (XCHUNK - 1)) == 0) {                  // prefetch next x chunk
            int nc = (t >> 10) + 1;                     // chunk index
            if (nc < T / XCHUNK) {
                float4 v = xg4[nc * (XCHUNK / 2) + p];  // 512 float4 per chunk, one per thread
                ((float4*)xs2)[(nc & 1) * (XCHUNK / 2) + p] = v;
            }
        }
        xv = xs2[(t + 1) & (2 * XCHUNK - 1)];           // next x, LDS broadcast
        asm volatile("bar.sync 0, 1024;" ::: "memory");
    }
    return hn;
}

// ---------------- Kernel B: sequential recurrence, 1 CTA ----------------
__global__ void __launch_bounds__(R, 1) esn_recur(
    const float* __restrict__ x,
    const float* __restrict__ h0,
    const float* __restrict__ Win,
    float*       __restrict__ hfinal,
    int write_hfinal)
{
    __shared__ float  hbuf[2 * R];
    __shared__ float2 xs2[2 * XCHUNK];    // 16KB x ring
    const int p   = threadIdx.x;
    const int row = g_rowof[p];

    const float w0 = Win[row * 2 + 0];
    const float w1 = Win[row * 2 + 1];
    const int mylen = g_plen[p];
    const int cls   = g_wclass[p >> 5];

    hbuf[p] = h0[row];
    const float4* xg4 = (const float4*)x;
    ((float4*)xs2)[p] = xg4[p];           // prologue: chunk 0 (512 float4 = 8KB)
    __syncthreads();

    float hn;
    switch (cls) {
        case  1: hn = run_loop< 1>(xg4, hbuf, xs2, p, mylen, w0, w1); break;
        case  2: hn = run_loop< 2>(xg4, hbuf, xs2, p, mylen, w0, w1); break;
        case  3: hn = run_loop< 3>(xg4, hbuf, xs2, p, mylen, w0, w1); break;
        case  4: hn = run_loop< 4>(xg4, hbuf, xs2, p, mylen, w0, w1); break;
        case  5: hn = run_loop< 5>(xg4, hbuf, xs2, p, mylen, w0, w1); break;
        case  6: hn = run_loop< 6>(xg4, hbuf, xs2, p, mylen, w0, w1); break;
        case  7: hn = run_loop< 7>(xg4, hbuf, xs2, p, mylen, w0, w1); break;
        case  8: hn = run_loop< 8>(xg4, hbuf, xs2, p, mylen, w0, w1); break;
        case  9: hn = run_loop< 9>(xg4, hbuf, xs2, p, mylen, w0, w1); break;
        case 10: hn = run_loop<10>(xg4, hbuf, xs2, p, mylen, w0, w1); break;
        case 11: hn = run_loop<11>(xg4, hbuf, xs2, p, mylen, w0, w1); break;
        case 12: hn = run_loop<12>(xg4, hbuf, xs2, p, mylen, w0, w1); break;
        case 13: hn = run_loop<13>(xg4, hbuf, xs2, p, mylen, w0, w1); break;
        case 14: hn = run_loop<14>(xg4, hbuf, xs2, p, mylen, w0, w1); break;
        case 15: hn = run_loop<15>(xg4, hbuf, xs2, p, mylen, w0, w1); break;
        case 16: hn = run_loop<16>(xg4, hbuf, xs2, p, mylen, w0, w1); break;
        case 20: hn = run_loop<20>(xg4, hbuf, xs2, p, mylen, w0, w1); break;
        case 24: hn = run_loop<24>(xg4, hbuf, xs2, p, mylen, w0, w1); break;
        case 28: hn = run_loop<28>(xg4, hbuf, xs2, p, mylen, w0, w1); break;
        default: hn = run_loop<32>(xg4, hbuf, xs2, p, mylen, w0, w1); break;
    }

    if (write_hfinal) hfinal[row] = hn;
}

// ---------------- Kernel C: readout GEMV (permuted states) ----------------
__global__ void __launch_bounds__(256) esn_readout(
    const float* __restrict__ Wout,
    const float* __restrict__ bias,
    float*       __restrict__ out)
{
    __shared__ float w0s[R];
    __shared__ float w1s[R];
    const int tid = threadIdx.x;
    for (int j = tid; j < R; j += 256) {
        int row = g_rowof[j];
        w0s[j] = Wout[row];
        w1s[j] = Wout[R + row];
    }
    __syncthreads();

    const int warp = tid >> 5;
    const int lane = tid & 31;
    const size_t t = (size_t)blockIdx.x * 8 + warp;
    if (t >= T) return;

    const float* __restrict__ s = g_states + t * R;
    float a0 = 0.0f, a1 = 0.0f;
#pragma unroll
    for (int k = 0; k < R / 32; ++k) {
        int j = lane + 32 * k;
        float v = __ldcs(s + j);
        a0 += v * w0s[j];
        a1 += v * w1s[j];
    }
#pragma unroll
    for (int o = 16; o; o >>= 1) {
        a0 += __shfl_down_sync(0xFFFFFFFFu, a0, o);
        a1 += __shfl_down_sync(0xFFFFFFFFu, a1, o);
    }
    if (lane == 0) {
        out[2 * t + 0] = a0 + bias[0];
        out[2 * t + 1] = a1 + bias[1];
    }
}

// ---------------- launch ----------------
extern "C" void kernel_launch(void* const* d_in, const int* in_sizes, int n_in,
                              void* d_out, int out_size)
{
    const float* x    = (const float*)d_in[0];
    const float* h0   = (const float*)d_in[1];
    const float* Win  = (const float*)d_in[2];
    const float* W    = (const float*)d_in[3];
    const float* Wout = (const float*)d_in[4];
    const float* bias = (const float*)d_in[5];

    float* out = (float*)d_out;
    const int need_hf = (out_size >= T * 2 + R) ? 1 : 0;
    float* hfinal = out + (size_t)T * 2;

    esn_extract<<<1, R>>>(W);
    esn_recur<<<1, R>>>(x, h0, Win, need_hf ? hfinal : out, need_hf);
    esn_readout<<<(T + 7) / 8, 256>>>(Wout, bias, out);
}

// round 6
// speedup vs baseline: 1.1440x; 1.1440x over previous
#include <cuda_runtime.h>
#include <cuda_bf16.h>
#include <cstdint>

#define R 512
#define T 65536
#define KMAX 32

// ---------------- device scratch ----------------
__device__ int   g_tcol[R * KMAX];      // [row][k] raw cols (phase1)
__device__ float g_tval[R * KMAX];
__device__ int   g_pc[R * KMAX];        // [thread][k] translated cols (phase3)
__device__ float g_pv[R * KMAX];
__device__ float g_val[KMAX * R];       // [slot][thread] scheduled ELL
__device__ int   g_col[KMAX * R];       // [slot][thread] smem float-index 0..1023 (2 copies)
__device__ int   g_ovfcol[R * KMAX];    // overflow CSR (normally empty)
__device__ float g_ovfval[R * KMAX];
__device__ int   g_ovfcnt[R];
__device__ int   g_rowof[R];
__device__ int   g_wclass[R / 32];
__device__ float g_states[(size_t)T * R];   // 128 MB, PERMUTED state trace

// ---------------- Kernel A: extract + length-sort + two-choice conflict-free schedule ----------------
__global__ void __launch_bounds__(R, 1) esn_extract(const float* __restrict__ W) {
    __shared__ int s_len[R];
    __shared__ int s_pos[R];
    __shared__ int s_rowof[R];
    __shared__ int s_cnt[KMAX + 1];
    __shared__ int s_base[KMAX + 1];

    const int p = threadIdx.x;

    // phase 1: per-row nnz scan
    int len = 0;
    for (int j = 0; j < R; ++j) {
        float v = W[p * R + j];
        if (v != 0.0f) {
            if (len < KMAX) { g_tcol[p * KMAX + len] = j; g_tval[p * KMAX + len] = v; }
            ++len;
        }
    }
    if (len > KMAX) len = KMAX;
    s_len[p] = len;
    if (p <= KMAX) s_cnt[p] = 0;
    __syncthreads();

    // phase 2: counting sort by len (ascending)
    atomicAdd(&s_cnt[len], 1);
    __syncthreads();
    if (p == 0) {
        int acc = 0;
        for (int l = 0; l <= KMAX; ++l) { s_base[l] = acc; acc += s_cnt[l]; }
    }
    __syncthreads();
    int pos = atomicAdd(&s_base[len], 1);
    s_pos[p] = pos;
    s_rowof[pos] = p;
    __syncthreads();

    // phase 3: thread p builds its translated entry list
    const int row   = s_rowof[p];
    const int mylen = s_len[row];
    g_rowof[p] = row;
    for (int k = 0; k < mylen; ++k) {
        g_pc[p * KMAX + k] = s_pos[g_tcol[row * KMAX + k]];
        g_pv[p * KMAX + k] = g_tval[row * KMAX + k];
    }
    g_ovfcnt[p] = 0;
    s_len[p] = mylen;               // now thread-indexed
    __syncthreads();

    // phase 4: lane 0 of each warp schedules with TWO bank choices per entry
    //   copy0: index c        -> bank  c & 31
    //   copy1: index 512+skew -> bank (c + (c>>5)) & 31
    if ((p & 31) == 0) {
        const int base = p;
        int      lens[32];
        unsigned taken[32];
        int total = 0;
        for (int i = 0; i < 32; ++i) {
            lens[i] = s_len[base + i];
            taken[i] = 0u;
            total += lens[i];
        }
        int s = 0;
        while (total > 0 && s < KMAX) {
            unsigned bankused = 0;
            int bankaddr[32];
            int aaddr[32];
            float aval[32];
            for (int i = 0; i < 32; ++i) {
                aaddr[i] = -1;
                const int li = lens[i];
                for (int e = 0; e < li; ++e) {
                    if ((taken[i] >> e) & 1u) continue;
                    int c  = g_pc[(base + i) * KMAX + e];
                    int b0 = c & 31;
                    int a0 = c;
                    int b1 = (c + (c >> 5)) & 31;
                    int a1 = 512 | (c & ~31) | b1;
                    int ub, ua;
                    if (!((bankused >> b0) & 1u) || bankaddr[b0] == a0) { ub = b0; ua = a0; }
                    else if (!((bankused >> b1) & 1u) || bankaddr[b1] == a1) { ub = b1; ua = a1; }
                    else continue;
                    bankused |= 1u << ub;
                    bankaddr[ub] = ua;
                    taken[i] |= 1u << e;
                    aaddr[i] = ua;
                    aval[i]  = g_pv[(base + i) * KMAX + e];
                    --total;
                    break;
                }
            }
            int fb = 0;
            for (int i = 0; i < 32; ++i) {
                if (aaddr[i] >= 0) {
                    g_col[s * R + base + i] = aaddr[i];
                    g_val[s * R + base + i] = aval[i];
                } else {
                    while ((bankused >> fb) & 1u) ++fb;     // always enough free banks
                    bankused |= 1u << fb;
                    g_col[s * R + base + i] = fb;           // copy0 index fb -> bank fb
                    g_val[s * R + base + i] = 0.0f;
                }
            }
            ++s;
        }
        if (total > 0) {            // pathological leftovers -> overflow CSR
            for (int i = 0; i < 32; ++i) {
                int oc = 0;
                for (int e = 0; e < lens[i]; ++e) {
                    if (!((taken[i] >> e) & 1u)) {
                        g_ovfcol[(base + i) * KMAX + oc] = g_pc[(base + i) * KMAX + e];
                        g_ovfval[(base + i) * KMAX + oc] = g_pv[(base + i) * KMAX + e];
                        ++oc;
                    }
                }
                g_ovfcnt[base + i] = oc;
            }
        }
        int cls = s;
        if (cls < 1) cls = 1;
        if (cls > 16) { cls = (cls + 3) & ~3; if (cls > KMAX) cls = KMAX; }
        // pad rounding slots (lane i -> bank i, conflict-free)
        for (int ss = s; ss < cls; ++ss)
            for (int i = 0; i < 32; ++i) {
                g_col[ss * R + base + i] = i;
                g_val[ss * R + base + i] = 0.0f;
            }
        g_wclass[base >> 5] = cls;
    }
}

// accurate fast tanh: 1 - 2/(e^{2x}+1), ~1e-6 abs err
__device__ __forceinline__ float tanh_acc(float x) {
    float e = __expf(2.0f * x);
    return 1.0f - __fdividef(2.0f, e + 1.0f);
}

// ---------------- templated recurrence body ----------------
template <int NK>
__device__ __forceinline__ float run_loop(const float2* __restrict__ xx,
                                          float* __restrict__ hbuf,   // [2][1024]
                                          int p, int oc, float w0, float w1)
{
    float rv[NK];
    int   rc[NK];   // byte offsets within one 4KB phase
#pragma unroll
    for (int k = 0; k < NK; ++k) {
        rv[k] = g_val[k * R + p];
        rc[k] = g_col[k * R + p] << 2;
    }
    const int skewidx = 512 | (p & ~31) | ((p + (p >> 5)) & 31);

    float* myst = g_states + p;
    float2 xv = xx[0];
    float hn = 0.0f;

    for (int t = 0; t < T; ++t) {
        const char* hr = (const char*)hbuf + ((t & 1) << 12);
        float acc0 = w0 * xv.x;
        float acc1 = w1 * xv.y;
#pragma unroll
        for (int k = 0; k < NK; ++k) {
            float hv = *(const float*)(hr + rc[k]);
            if (k & 1) acc1 = fmaf(rv[k], hv, acc1);
            else       acc0 = fmaf(rv[k], hv, acc0);
        }
        if (oc) {   // warp-uniformly 0 in practice; correctness backstop (copy0 indices)
            for (int k = 0; k < oc; ++k)
                acc0 = fmaf(g_ovfval[p * KMAX + k],
                            ((const float*)hr)[g_ovfcol[p * KMAX + k]], acc0);
        }
        hn = tanh_acc(acc0 + acc1);
        float* hw = hbuf + (((t + 1) & 1) << 10);
        hw[p] = hn;                                      // copy0
        hw[skewidx] = hn;                                // copy1 (skewed, conflict-free)

        asm volatile("bar.arrive 0, 1024;" ::: "memory");
        // off-critical-path window:
        *myst = hn;  myst += R;                          // states STG, fire-and-forget
        int tn = (t + 1 < T) ? (t + 1) : (T - 1);
        xv = xx[tn];                                     // prefetch next x
        asm volatile("bar.sync 0, 1024;" ::: "memory");
    }
    return hn;
}

// ---------------- Kernel B: sequential recurrence, 1 CTA ----------------
__global__ void __launch_bounds__(R, 1) esn_recur(
    const float* __restrict__ x,
    const float* __restrict__ h0,
    const float* __restrict__ Win,
    float*       __restrict__ hfinal,
    int write_hfinal)
{
    __shared__ float hbuf[2 * 1024];      // [phase][copy0:512 | copy1:512]
    const int p   = threadIdx.x;
    const int row = g_rowof[p];

    const float w0 = Win[row * 2 + 0];
    const float w1 = Win[row * 2 + 1];
    const int oc  = g_ovfcnt[p];
    const int cls = g_wclass[p >> 5];

    float h0v = h0[row];
    hbuf[p] = h0v;
    hbuf[512 | (p & ~31) | ((p + (p >> 5)) & 31)] = h0v;
    __syncthreads();

    const float2* xx = (const float2*)x;
    float hn;
    switch (cls) {
        case  1: hn = run_loop< 1>(xx, hbuf, p, oc, w0, w1); break;
        case  2: hn = run_loop< 2>(xx, hbuf, p, oc, w0, w1); break;
        case  3: hn = run_loop< 3>(xx, hbuf, p, oc, w0, w1); break;
        case  4: hn = run_loop< 4>(xx, hbuf, p, oc, w0, w1); break;
        case  5: hn = run_loop< 5>(xx, hbuf, p, oc, w0, w1); break;
        case  6: hn = run_loop< 6>(xx, hbuf, p, oc, w0, w1); break;
        case  7: hn = run_loop< 7>(xx, hbuf, p, oc, w0, w1); break;
        case  8: hn = run_loop< 8>(xx, hbuf, p, oc, w0, w1); break;
        case  9: hn = run_loop< 9>(xx, hbuf, p, oc, w0, w1); break;
        case 10: hn = run_loop<10>(xx, hbuf, p, oc, w0, w1); break;
        case 11: hn = run_loop<11>(xx, hbuf, p, oc, w0, w1); break;
        case 12: hn = run_loop<12>(xx, hbuf, p, oc, w0, w1); break;
        case 13: hn = run_loop<13>(xx, hbuf, p, oc, w0, w1); break;
        case 14: hn = run_loop<14>(xx, hbuf, p, oc, w0, w1); break;
        case 15: hn = run_loop<15>(xx, hbuf, p, oc, w0, w1); break;
        case 16: hn = run_loop<16>(xx, hbuf, p, oc, w0, w1); break;
        case 20: hn = run_loop<20>(xx, hbuf, p, oc, w0, w1); break;
        case 24: hn = run_loop<24>(xx, hbuf, p, oc, w0, w1); break;
        case 28: hn = run_loop<28>(xx, hbuf, p, oc, w0, w1); break;
        default: hn = run_loop<32>(xx, hbuf, p, oc, w0, w1); break;
    }

    if (write_hfinal) hfinal[row] = hn;   // un-permute once
}

// ---------------- Kernel C: readout GEMV (permuted states) ----------------
__global__ void __launch_bounds__(256) esn_readout(
    const float* __restrict__ Wout,
    const float* __restrict__ bias,
    float*       __restrict__ out)
{
    __shared__ float w0s[R];
    __shared__ float w1s[R];
    const int tid = threadIdx.x;
    for (int j = tid; j < R; j += 256) {
        int row = g_rowof[j];
        w0s[j] = Wout[row];
        w1s[j] = Wout[R + row];
    }
    __syncthreads();

    const int warp = tid >> 5;
    const int lane = tid & 31;
    const size_t t = (size_t)blockIdx.x * 8 + warp;
    if (t >= T) return;

    const float* __restrict__ s = g_states + t * R;
    float a0 = 0.0f, a1 = 0.0f;
#pragma unroll
    for (int k = 0; k < R / 32; ++k) {
        int j = lane + 32 * k;
        float v = s[j];
        a0 += v * w0s[j];
        a1 += v * w1s[j];
    }
#pragma unroll
    for (int o = 16; o; o >>= 1) {
        a0 += __shfl_down_sync(0xFFFFFFFFu, a0, o);
        a1 += __shfl_down_sync(0xFFFFFFFFu, a1, o);
    }
    if (lane == 0) {
        out[2 * t + 0] = a0 + bias[0];
        out[2 * t + 1] = a1 + bias[1];
    }
}

// ---------------- launch ----------------
extern "C" void kernel_launch(void* const* d_in, const int* in_sizes, int n_in,
                              void* d_out, int out_size)
{
    const float* x    = (const float*)d_in[0];
    const float* h0   = (const float*)d_in[1];
    const float* Win  = (const float*)d_in[2];
    const float* W    = (const float*)d_in[3];
    const float* Wout = (const float*)d_in[4];
    const float* bias = (const float*)d_in[5];

    float* out = (float*)d_out;
    const int need_hf = (out_size >= T * 2 + R) ? 1 : 0;
    float* hfinal = out + (size_t)T * 2;

    esn_extract<<<1, R>>>(W);
    esn_recur<<<1, R>>>(x, h0, Win, need_hf ? hfinal : out, need_hf);
    esn_readout<<<(T + 7) / 8, 256>>>(Wout, bias, out);
}